// round 16
// baseline (speedup 1.0000x reference)
#include <cuda_runtime.h>
#include <cstdint>

#define M_GT 128
#define M_CHUNK 8               // per block: two quads of 4 gts
#define N_MCHUNK 16
#define TPB 256
#define A_PER 2
#define TILE (TPB * A_PER)      // 512 anchors per block
#define MAX_NB 512              // anchor-block columns; supports N up to 262144
#define MAX_N 262144

// Scratch (allocation-free: __device__ globals)
__device__ unsigned g_bits[N_MCHUNK][MAX_N];        // per-anchor max iou BITS per gt-chunk
__device__ unsigned char g_j[N_MCHUNK][MAX_N];      // per-anchor local argmax (0..7) per chunk
__device__ unsigned long long g_part[M_GT][MAX_NB]; // per-(gt, anchor-block) packed best
__device__ unsigned char g_flag[MAX_N];             // forced-anchor flags (self-clearing)

// Correctly-rounded fp32 division for normal operands (Markstein fast path, no guard).
// Bit-identical to div.rn for our operand ranges (verified: rel_err constant across rounds).
__device__ __forceinline__ float exact_div(float num, float den) {
    float r0; asm("rcp.approx.f32 %0, %1;" : "=f"(r0) : "f"(den));
    float e  = __fmaf_rn(-den, r0, 1.0f);
    float r1 = __fmaf_rn(r0, e, r0);
    float y  = __fmul_rn(num, r1);
    float rr = __fmaf_rn(-den, y, num);
    return __fmaf_rn(rr, r1, y);
}

// ---------- Kernel B: 2D grid: x = anchor tile (512), y = gt chunk (8) ----------
// Inner loop branch-free. Argmax tracked via packed keys + single IMNMX per pair:
//   iou <= 1.0 -> bits <= 0x3F800000 (30 bits), so 2 low bits are free for tags.
//   rowkey = (bits<<2)|(3-mm): tie in bits -> smaller mm wins (first-max).
//   colkey = (bits<<1)|(1-k):  tie in bits -> k=0 (smaller anchor index) wins.
__global__ __launch_bounds__(TPB) void iou_kernel(const float4* __restrict__ anchors,
                                                  const float4* __restrict__ gtb,
                                                  int N) {
    __shared__ float4 s_gt[M_CHUNK];
    __shared__ float  s_area[M_CHUNK];
    __shared__ unsigned long long s_best[M_CHUNK];

    const int t = threadIdx.x;
    const int mbase = blockIdx.y * M_CHUNK;
    if (t < M_CHUNK) {
        float4 g = gtb[mbase + t];
        s_gt[t] = g;
        s_area[t] = (g.z - g.x) * (g.w - g.y);
        s_best[t] = 0x00000000FFFFFFFFull;   // iou=0, idx = ~0xFFFFFFFF = 0 (all-zero column)
    }
    __syncthreads();

    const int lane = t & 31;
    const int base = blockIdx.x * TILE;
    const int bt   = base + t;

    float4 a[A_PER];
    float  area_a[A_PER];
    #pragma unroll
    for (int k = 0; k < A_PER; k++) {
        int i = bt + k * TPB;              // k=0 has the smaller anchor index
        // OOB: degenerate far-away anchor -> iou computes to exactly 0 (maskless)
        float4 av = (i < N) ? anchors[i] : make_float4(3e8f, 3e8f, 3e8f, 3e8f);
        a[k] = av;
        area_a[k] = (av.z - av.x) * (av.w - av.y);
    }

    unsigned colkey[M_CHUNK];
    #pragma unroll
    for (int m = 0; m < M_CHUNK; m++) colkey[m] = 0u;

    unsigned rowbits[A_PER] = {0u, 0u};
    int      rowj[A_PER]    = {0, 0};

    #pragma unroll
    for (int q = 0; q < 2; q++) {
        unsigned rowkey[A_PER] = {0u, 0u};     // quad-local row keys
        #pragma unroll
        for (int mm = 0; mm < 4; mm++) {
            const int m = q * 4 + mm;
            const float4 g  = s_gt[m];
            const float  ab = s_area[m];
            #pragma unroll
            for (int k = 0; k < A_PER; k++) {
                float lx = fmaxf(a[k].x, g.x);
                float ly = fmaxf(a[k].y, g.y);
                float rx = fminf(a[k].z, g.z);
                float ry = fminf(a[k].w, g.w);
                float w = fmaxf(rx - lx, 0.0f);
                float h = fmaxf(ry - ly, 0.0f);
                float inter = w * h;
                float uni = (area_a[k] + ab) - inter;    // same association as reference
                float iou = exact_div(inter, uni);       // == div.rn
                unsigned b = __float_as_uint(iou);       // iou in [0,1] -> bits monotone, <=30 bits

                rowkey[k] = umax(rowkey[k], (b << 2) | (unsigned)(3 - mm));
                colkey[m] = umax(colkey[m], (b << 1) | (unsigned)(1 - k));
            }
        }
        // merge quad into per-anchor row state (strict > keeps earlier quad on bit-tie)
        #pragma unroll
        for (int k = 0; k < A_PER; k++) {
            unsigned qb = rowkey[k] >> 2;
            int      qm = q * 4 + (3 - (int)(rowkey[k] & 3u));
            if (qb > rowbits[k]) { rowbits[k] = qb; rowj[k] = qm; }
        }
    }

    const int by = blockIdx.y;
    #pragma unroll
    for (int k = 0; k < A_PER; k++) {
        int i = bt + k * TPB;
        if (i < N) {
            g_bits[by][i] = rowbits[k];
            g_j[by][i]    = (unsigned char)rowj[k];
        }
    }

    // Deferred per-gt column argmax: once per warp per gt (8 total).
    #pragma unroll
    for (int m = 0; m < M_CHUNK; m++) {
        unsigned key  = colkey[m];
        unsigned wmax = __reduce_max_sync(0xFFFFFFFFu, key);
        if (wmax > 1u) {                      // bits > 0 (sentinels/zero columns excluded)
            int kwin = 1 - (int)(wmax & 1u);
            unsigned myidx = (unsigned)(bt + kwin * TPB);
            unsigned cand  = (key == wmax) ? myidx : 0xFFFFFFFFu;
            unsigned widx  = __reduce_min_sync(0xFFFFFFFFu, cand);  // first index on tie
            if (lane == 0) {
                atomicMax(&s_best[m],
                          ((unsigned long long)(wmax >> 1) << 32) |
                          (unsigned long long)(~widx));
            }
        }
    }

    __syncthreads();
    if (t < M_CHUNK) g_part[mbase + t][blockIdx.x] = s_best[t];
}

// ---------- Kernel R: per-gt winner across blocks -> scatter forced flags ----------
__global__ void reduce_kernel(int NB) {
    const int m = blockIdx.x;        // 128 blocks x 32 threads
    const int lane = threadIdx.x;
    unsigned long long best = 0x00000000FFFFFFFFull;
    for (int b = lane; b < NB; b += 32) {
        unsigned long long v = g_part[m][b];
        if (v > best) best = v;
    }
    #pragma unroll
    for (int o = 16; o > 0; o >>= 1) {
        unsigned long long v = __shfl_down_sync(0xFFFFFFFFu, best, o);
        if (v > best) best = v;
    }
    if (lane == 0) {
        unsigned idx = ~(unsigned)(best & 0xFFFFFFFFull);
        g_flag[idx] = 1;             // read + cleared by out_kernel (graph-replay safe)
    }
}

// ---------- Kernel C: merge chunks, classify, label + encode, write all outputs ----------
#define TPB_OUT 256
__global__ __launch_bounds__(TPB_OUT) void out_kernel(const float4* __restrict__ anchors,
                                                      const float4* __restrict__ gtb,
                                                      const int* __restrict__ labels,
                                                      float* __restrict__ out, int N) {
    __shared__ float4 s_gt[M_GT];
    __shared__ int    s_lab[M_GT];

    const int t = threadIdx.x;
    if (t < M_GT) {
        s_gt[t]  = gtb[t];
        s_lab[t] = labels[t];
    }
    __syncthreads();

    const int i = blockIdx.x * TPB_OUT + t;
    if (i >= N) return;

    // merge 16 gt-chunks: strict > in ascending chunk order = global first-max
    unsigned mb = g_bits[0][i];
    int j = (int)g_j[0][i];
    #pragma unroll
    for (int c = 1; c < N_MCHUNK; c++) {
        unsigned b = g_bits[c][i];
        int jj = (int)g_j[c][i] + c * M_CHUNK;
        if (b > mb) { mb = b; j = jj; }
    }
    float maxiou = __uint_as_float(mb);

    bool forced = (g_flag[i] != 0);
    g_flag[i] = 0;                             // self-clear for next graph replay
    bool pos = (maxiou >= 0.5f) || forced;
    bool neg = (maxiou < 0.4f) && !pos;
    int  cls = pos ? s_lab[j] : (neg ? 0 : -1);

    float4 a = anchors[i];
    float4 g = s_gt[j];

    const float eps = 1.19209290e-07f;  // FLT_EPSILON == jnp.finfo(float32).eps
    float ax = (a.x + a.z) * 0.5f;
    float ay = (a.y + a.w) * 0.5f;
    float aw = fmaxf(a.z - a.x, eps);
    float ah = fmaxf(a.w - a.y, eps);
    float gx = (g.x + g.z) * 0.5f;
    float gy = (g.y + g.w) * 0.5f;
    float gw = g.z - g.x;
    float gh = g.w - g.y;

    float dx = (gx - ax) / aw;
    float dy = (gy - ay) / ah;
    float dw = logf(gw / aw);
    float dh = logf(gh / ah);

    // output layout (float32): [cls (N)] [reg (N,4)] [pos (N)]
    out[i] = (float)cls;
    float4 r = pos ? make_float4(dx, dy, dw, dh) : make_float4(0.f, 0.f, 0.f, 0.f);
    reinterpret_cast<float4*>(out + N)[i] = r;   // out+N is 16B-aligned (N multiple of 4)
    out[5 * N + i] = pos ? 1.0f : 0.0f;
}

extern "C" void kernel_launch(void* const* d_in, const int* in_sizes, int n_in,
                              void* d_out, int out_size) {
    const float4* anchors = (const float4*)d_in[0];
    const float4* gtb     = (const float4*)d_in[1];
    const int*    labels  = (const int*)d_in[2];
    float* out = (float*)d_out;
    const int N = in_sizes[0] / 4;
    const int NBx = (N + TILE - 1) / TILE;

    dim3 grid(NBx, N_MCHUNK);
    iou_kernel<<<grid, TPB>>>(anchors, gtb, N);
    reduce_kernel<<<M_GT, 32>>>(NBx);
    out_kernel<<<(N + TPB_OUT - 1) / TPB_OUT, TPB_OUT>>>(anchors, gtb, labels, out, N);
}